// round 9
// baseline (speedup 1.0000x reference)
#include <cuda_runtime.h>

#define Bv 4
#define Tv 256
#define Ev 512
#define Hv 8
#define Sv 64

typedef unsigned long long u64;

// packed fp32x2 helpers (FFMA2 path — ptxas never emits this from C++)
__device__ __forceinline__ u64 pk2(float x, float y) {
    u64 r; asm("mov.b64 %0,{%1,%2};" : "=l"(r) : "f"(x), "f"(y)); return r;
}
__device__ __forceinline__ void upk2(u64 v, float& x, float& y) {
    asm("mov.b64 {%0,%1},%2;" : "=f"(x), "=f"(y) : "l"(v));
}
__device__ __forceinline__ void fma2(u64& d, u64 a, u64 b) {
    asm("fma.rn.f32x2 %0,%1,%2,%0;" : "+l"(d) : "l"(a), "l"(b));
}
__device__ __forceinline__ u64 add2(u64 a, u64 b) {
    u64 r; asm("add.rn.f32x2 %0,%1,%2;" : "=l"(r) : "l"(a), "l"(b)); return r;
}

// scratch (allocation-free rule: __device__ globals)
__device__ float g_q[Bv*Tv*Ev];
__device__ float g_k[Bv*Tv*Ev];
__device__ float g_v[Bv*Tv*Ev];
__device__ float g_vec[Bv*Tv*Ev];

// ---------------------------------------------------------------------------
// K1: q/k/v projections, tiled GEMM, one weight per blockIdx.z.
// grid = (16 token-tiles, 8 heads, 3 weights), 256 threads.
// ---------------------------------------------------------------------------
__global__ void __launch_bounds__(256) qkv_kernel(const float* __restrict__ x,
                                                  const float* __restrict__ Wq,
                                                  const float* __restrict__ Wk,
                                                  const float* __restrict__ Wv)
{
    __shared__ float xs[64][68];   // [d][token]
    __shared__ float ws[64][68];   // [d][o]
    const int t0  = blockIdx.x * 64;
    const int n   = blockIdx.y;
    const int w   = blockIdx.z;
    const int tid = threadIdx.x;
    const int ty  = tid >> 4, tx = tid & 15;

    const float* Wlist[3] = {Wq, Wk, Wv};
    float*       Olist[3] = {g_q, g_k, g_v};
    const float* W = Wlist[w];

    #pragma unroll
    for (int ch = tid; ch < 1024; ch += 256) {
        const int r = ch >> 4, d = (ch & 15) * 4;
        const float4 v4 = *(const float4*)&x[(size_t)(t0 + r)*Ev + n*Sv + d];
        xs[d][r] = v4.x; xs[d+1][r] = v4.y; xs[d+2][r] = v4.z; xs[d+3][r] = v4.w;
        const float4 w4 = *(const float4*)&W[r*Sv + d];
        ws[d][r] = w4.x; ws[d+1][r] = w4.y; ws[d+2][r] = w4.z; ws[d+3][r] = w4.w;
    }
    __syncthreads();

    u64 accp[4][2];
    #pragma unroll
    for (int r = 0; r < 4; r++) { accp[r][0] = pk2(0.f,0.f); accp[r][1] = pk2(0.f,0.f); }

    #pragma unroll 8
    for (int k = 0; k < 64; k++) {
        const float4 a4 = *(const float4*)&xs[k][ty*4];
        const float4 b4 = *(const float4*)&ws[k][tx*4];
        const u64 b01 = pk2(b4.x, b4.y), b23 = pk2(b4.z, b4.w);
        const float a[4] = {a4.x, a4.y, a4.z, a4.w};
        #pragma unroll
        for (int r = 0; r < 4; r++) {
            const u64 aa = pk2(a[r], a[r]);
            fma2(accp[r][0], aa, b01);
            fma2(accp[r][1], aa, b23);
        }
    }

    float* O = Olist[w];
    #pragma unroll
    for (int r = 0; r < 4; r++) {
        float4 o;
        upk2(accp[r][0], o.x, o.y);
        upk2(accp[r][1], o.z, o.w);
        *(float4*)&O[(size_t)(t0 + ty*4 + r)*Ev + n*Sv + tx*4] = o;
    }
}

// ---------------------------------------------------------------------------
// K2: fused attention with smem-resident k/v (kills the L2 re-read traffic).
// CTA = (b, head n, 32-i tile). 512 threads = 16 warps; warp w owns 16 j's.
// smem: k[256][64] + v[256][64] + q[32][64] + score/prob/partials = ~142 KB.
// ---------------------------------------------------------------------------
#define AT_SMEM_FLOATS (16384 + 16384 + 2048 + 256 + 256 + 32 + 1024)
__global__ void __launch_bounds__(512) attn_kernel(const float* __restrict__ ek,
                                                   const float* __restrict__ ev,
                                                   const int*   __restrict__ mask)
{
    extern __shared__ float smem[];
    float* ks     = smem;               // 256*64
    float* vs     = ks + 16384;         // 256*64
    float* qs     = vs + 16384;         // 32*64
    float* scores = qs + 2048;          // 256
    float* prob   = scores + 256;       // 256
    float* wred   = prob + 256;         // 32: [0..7]=max, [16..23]=sum
    float* part   = wred + 32;          // 16*64

    const int bid  = blockIdx.x;
    const int n    = bid & 7;
    const int b    = (bid >> 3) & 3;
    const int i0   = (bid >> 5) * 32;
    const int tid  = threadIdx.x;
    const int warp = tid >> 5;
    const int lane = tid & 31;
    const int jb   = warp * 16;         // this warp's j range

    // load k/v tiles for (b, n): 256 rows x 64 d
    const float4* k4 = (const float4*)g_k;
    const float4* v4 = (const float4*)g_v;
    for (int idx = tid; idx < 4096; idx += 512) {
        const int j = idx >> 4, c = idx & 15;
        const int src = ((b*Tv + j)*Hv + n)*16 + c;
        ((float4*)ks)[j*16 + c] = k4[src];
        ((float4*)vs)[j*16 + c] = v4[src];
    }
    // q tile for i0..i0+31
    {
        const int r = tid >> 4, c = tid & 15;
        ((float4*)qs)[r*16 + c] = ((const float4*)g_q)[((b*Tv + i0 + r)*Hv + n)*16 + c];
    }
    __syncthreads();

    for (int ii = 0; ii < 32; ii++) {
        const int i = i0 + ii;
        const float q0 = qs[ii*64 + 2*lane];
        const float q1 = qs[ii*64 + 2*lane + 1];

        // ---- Pass A: score[j] = q.(k[j] + ek[i,j]) ----
        const float2* ekp = (const float2*)ek
            + ((size_t)(b*Tv + i)*Tv + jb)*256 + n*32 + lane;
        float2 re[16];
        #pragma unroll
        for (int u = 0; u < 16; u++) re[u] = ekp[u*256];
        #pragma unroll
        for (int u = 0; u < 16; u++) {
            const int j = jb + u;
            const float2 kk = *(const float2*)&ks[j*64 + 2*lane];
            float p = fmaf(re[u].x + kk.x, q0, (re[u].y + kk.y) * q1);
            p += __shfl_xor_sync(0xffffffffu, p, 16);
            p += __shfl_xor_sync(0xffffffffu, p, 8);
            p += __shfl_xor_sync(0xffffffffu, p, 4);
            p += __shfl_xor_sync(0xffffffffu, p, 2);
            p += __shfl_xor_sync(0xffffffffu, p, 1);
            if (lane == 0) scores[j] = p;
        }
        __syncthreads();

        // ---- softmax over 256 j (threads 0..255) ----
        float sv = 0.f;
        if (tid < 256) {
            sv = scores[tid];
            sv = (mask[((size_t)b*Tv + i)*Tv + tid] == 0) ? -1e9f : sv * 0.125f;
            float m = sv;
            m = fmaxf(m, __shfl_xor_sync(0xffffffffu, m, 16));
            m = fmaxf(m, __shfl_xor_sync(0xffffffffu, m, 8));
            m = fmaxf(m, __shfl_xor_sync(0xffffffffu, m, 4));
            m = fmaxf(m, __shfl_xor_sync(0xffffffffu, m, 2));
            m = fmaxf(m, __shfl_xor_sync(0xffffffffu, m, 1));
            if (lane == 0) wred[warp] = m;
        }
        __syncthreads();
        if (tid < 256) {
            float m = wred[0];
            #pragma unroll
            for (int w = 1; w < 8; w++) m = fmaxf(m, wred[w]);
            const float e = expf(sv - m);
            prob[tid] = e;
            float su = e;
            su += __shfl_xor_sync(0xffffffffu, su, 16);
            su += __shfl_xor_sync(0xffffffffu, su, 8);
            su += __shfl_xor_sync(0xffffffffu, su, 4);
            su += __shfl_xor_sync(0xffffffffu, su, 2);
            su += __shfl_xor_sync(0xffffffffu, su, 1);
            if (lane == 0) wred[16 + warp] = su;
        }
        __syncthreads();

        // ---- Pass B: acc += e[j] * (v[j] + ev[i,j]) over this warp's 16 j ----
        const float2* evp = (const float2*)ev
            + ((size_t)(b*Tv + i)*Tv + jb)*256 + n*32 + lane;
        float2 rv[16];
        #pragma unroll
        for (int u = 0; u < 16; u++) rv[u] = evp[u*256];
        u64 acc = pk2(0.f, 0.f);
        #pragma unroll
        for (int u = 0; u < 16; u++) {
            const int j = jb + u;
            const float2 vv = *(const float2*)&vs[j*64 + 2*lane];
            const float p = prob[j];
            fma2(acc, pk2(p, p), add2(pk2(rv[u].x, rv[u].y), pk2(vv.x, vv.y)));
        }
        float ax, ay; upk2(acc, ax, ay);
        *(float2*)&part[warp*64 + 2*lane] = make_float2(ax, ay);
        __syncthreads();

        // ---- reduce 16 warp-partials, normalize, write out (threads 0..31) ----
        if (tid < 32) {
            float s0 = 0.f, s1 = 0.f;
            #pragma unroll
            for (int w = 0; w < 16; w++) {
                s0 += part[w*64 + 2*tid];
                s1 += part[w*64 + 2*tid + 1];
            }
            float tot = 0.f;
            #pragma unroll
            for (int w = 0; w < 8; w++) tot += wred[16 + w];
            const float inv = 1.f / tot;
            *(float2*)&g_vec[((size_t)(b*Tv + i)*Hv + n)*Sv + 2*tid] =
                make_float2(s0 * inv, s1 * inv);
        }
        // no barrier needed here: next writes to part come after 3 barriers
    }
}

// ---------------------------------------------------------------------------
// K3: out = vec @ Wu^T + bu.  BM=32, BN=32, BK=32, 128 threads, 512 CTAs.
// ---------------------------------------------------------------------------
__global__ void __launch_bounds__(128) proj_kernel(const float* __restrict__ Wu,
                                                   const float* __restrict__ bu,
                                                   float* __restrict__ out)
{
    __shared__ float As[32][36];   // [k][r]
    __shared__ float Bs[32][36];   // [k][c]
    const int r0  = blockIdx.x * 32;
    const int c0  = blockIdx.y * 32;
    const int tid = threadIdx.x;
    const int ty  = tid >> 4;       // 0..7  -> rows ty*4..+3
    const int tx  = tid & 15;       // 0..15 -> cols tx*2..+1

    u64 accp[4];
    #pragma unroll
    for (int r = 0; r < 4; r++) accp[r] = pk2(0.f, 0.f);

    for (int k0 = 0; k0 < Ev; k0 += 32) {
        __syncthreads();
        #pragma unroll
        for (int ch = tid; ch < 256; ch += 128) {
            const int r = ch >> 3, k = (ch & 7) * 4;
            const float4 v4 = *(const float4*)&g_vec[(size_t)(r0 + r)*Ev + k0 + k];
            As[k][r] = v4.x; As[k+1][r] = v4.y; As[k+2][r] = v4.z; As[k+3][r] = v4.w;
        }
        #pragma unroll
        for (int ch = tid; ch < 256; ch += 128) {
            const int c = ch >> 3, k = (ch & 7) * 4;
            const float4 v4 = *(const float4*)&Wu[(size_t)(c0 + c)*Ev + k0 + k];
            Bs[k][c] = v4.x; Bs[k+1][c] = v4.y; Bs[k+2][c] = v4.z; Bs[k+3][c] = v4.w;
        }
        __syncthreads();

        #pragma unroll 8
        for (int k = 0; k < 32; k++) {
            const float4 a4 = *(const float4*)&As[k][ty*4];
            const float2 b2 = *(const float2*)&Bs[k][tx*2];
            const u64 bb = pk2(b2.x, b2.y);
            const float a[4] = {a4.x, a4.y, a4.z, a4.w};
            #pragma unroll
            for (int ry = 0; ry < 4; ry++)
                fma2(accp[ry], pk2(a[ry], a[ry]), bb);
        }
    }

    const float2 bias = *(const float2*)&bu[c0 + tx*2];
    #pragma unroll
    for (int ry = 0; ry < 4; ry++) {
        float2 o;
        upk2(accp[ry], o.x, o.y);
        o.x += bias.x; o.y += bias.y;
        *(float2*)&out[(size_t)(r0 + ty*4 + ry)*Ev + c0 + tx*2] = o;
    }
}

// ---------------------------------------------------------------------------
extern "C" void kernel_launch(void* const* d_in, const int* in_sizes, int n_in,
                              void* d_out, int out_size)
{
    const float* x   = (const float*)d_in[0];
    const float* rk  = (const float*)d_in[1];
    const float* rv  = (const float*)d_in[2];
    const int*   msk = (const int*)  d_in[3];
    const float* Wq  = (const float*)d_in[4];
    const float* Wk  = (const float*)d_in[5];
    const float* Wv  = (const float*)d_in[6];
    const float* Wu  = (const float*)d_in[7];
    const float* bu  = (const float*)d_in[8];
    float* out = (float*)d_out;

    const int at_smem = AT_SMEM_FLOATS * 4;
    cudaFuncSetAttribute(attn_kernel, cudaFuncAttributeMaxDynamicSharedMemorySize, at_smem);

    qkv_kernel<<<dim3(16, Hv, 3), 256>>>(x, Wq, Wk, Wv);
    attn_kernel<<<256, 512, at_smem>>>(rk, rv, msk);
    proj_kernel<<<dim3(32, 16), 128>>>(Wu, bu, out);
}

// round 10
// speedup vs baseline: 1.4134x; 1.4134x over previous
#include <cuda_runtime.h>

#define Bv 4
#define Tv 256
#define Ev 512
#define Hv 8
#define Sv 64

typedef unsigned long long u64;

// packed fp32x2 helpers (FFMA2 path — ptxas never emits this from C++)
__device__ __forceinline__ u64 pk2(float x, float y) {
    u64 r; asm("mov.b64 %0,{%1,%2};" : "=l"(r) : "f"(x), "f"(y)); return r;
}
__device__ __forceinline__ void upk2(u64 v, float& x, float& y) {
    asm("mov.b64 {%0,%1},%2;" : "=f"(x), "=f"(y) : "l"(v));
}
__device__ __forceinline__ void fma2(u64& d, u64 a, u64 b) {
    asm("fma.rn.f32x2 %0,%1,%2,%0;" : "+l"(d) : "l"(a), "l"(b));
}
__device__ __forceinline__ u64 add2(u64 a, u64 b) {
    u64 r; asm("add.rn.f32x2 %0,%1,%2;" : "=l"(r) : "l"(a), "l"(b)); return r;
}

// scratch (allocation-free rule: __device__ globals)
__device__ float g_q[Bv*Tv*Ev];
__device__ float g_k[Bv*Tv*Ev];
__device__ float g_v[Bv*Tv*Ev];
__device__ float g_vec[Bv*Tv*Ev];

// ---------------------------------------------------------------------------
// K1: q/k/v projections (R8 version — measured 13.1us).
// grid = (16 token-tiles, 8 heads), 256 threads; x tile reused for 3 weights.
// ---------------------------------------------------------------------------
__global__ void __launch_bounds__(256) qkv_kernel(const float* __restrict__ x,
                                                  const float* __restrict__ Wq,
                                                  const float* __restrict__ Wk,
                                                  const float* __restrict__ Wv)
{
    __shared__ float xs[64][68];   // [d][token]
    __shared__ float ws[64][68];   // [d][o]
    const int t0  = blockIdx.x * 64;
    const int n   = blockIdx.y;
    const int tid = threadIdx.x;
    const int ty  = tid >> 4, tx = tid & 15;

    #pragma unroll
    for (int ch = tid; ch < 1024; ch += 256) {
        const int r = ch >> 4, d = (ch & 15) * 4;
        const float4 v4 = *(const float4*)&x[(size_t)(t0 + r)*Ev + n*Sv + d];
        xs[d][r] = v4.x; xs[d+1][r] = v4.y; xs[d+2][r] = v4.z; xs[d+3][r] = v4.w;
    }

    const float* Wlist[3] = {Wq, Wk, Wv};
    float*       Olist[3] = {g_q, g_k, g_v};

    #pragma unroll
    for (int w = 0; w < 3; w++) {
        __syncthreads();
        const float* W = Wlist[w];
        #pragma unroll
        for (int ch = tid; ch < 1024; ch += 256) {
            const int o = ch >> 4, d = (ch & 15) * 4;
            const float4 v4 = *(const float4*)&W[o*Sv + d];
            ws[d][o] = v4.x; ws[d+1][o] = v4.y; ws[d+2][o] = v4.z; ws[d+3][o] = v4.w;
        }
        __syncthreads();

        u64 accp[4][2];
        #pragma unroll
        for (int r = 0; r < 4; r++) { accp[r][0] = pk2(0.f,0.f); accp[r][1] = pk2(0.f,0.f); }

        #pragma unroll 8
        for (int k = 0; k < 64; k++) {
            const float4 a4 = *(const float4*)&xs[k][ty*4];
            const float4 b4 = *(const float4*)&ws[k][tx*4];
            const u64 b01 = pk2(b4.x, b4.y), b23 = pk2(b4.z, b4.w);
            const float a[4] = {a4.x, a4.y, a4.z, a4.w};
            #pragma unroll
            for (int r = 0; r < 4; r++) {
                const u64 aa = pk2(a[r], a[r]);
                fma2(accp[r][0], aa, b01);
                fma2(accp[r][1], aa, b23);
            }
        }

        float* O = Olist[w];
        #pragma unroll
        for (int r = 0; r < 4; r++) {
            float4 o;
            upk2(accp[r][0], o.x, o.y);
            upk2(accp[r][1], o.z, o.w);
            *(float4*)&O[(size_t)(t0 + ty*4 + r)*Ev + n*Sv + tx*4] = o;
        }
    }
}

// ---------------------------------------------------------------------------
// K2: fused attention. One CTA per (b,i), 256 threads.
// Pass A (NEW, shuffle-free): per 32-j chunk, all threads load (ek+k) rows
// coalesced into padded smem; then thread (head=warp, j=lane) does a private
// 64-d dot from smem. Pass B unchanged (R8): stream ev + L2 v, 8-deep MLP.
// ---------------------------------------------------------------------------
#define BUF_STRIDE 129                       // float4 units per row (pad 1)
#define AT_SMEM_BYTES (32*BUF_STRIDE*16 + 8*256*4 + 512*4)
__global__ void __launch_bounds__(256) attn_kernel(const float* __restrict__ ek,
                                                   const float* __restrict__ ev,
                                                   const int*   __restrict__ mask)
{
    extern __shared__ float smem[];
    float4* buf = (float4*)smem;                         // 32 rows x 129 f4
    float (*sc)[Tv] = (float (*)[Tv])(smem + 32*BUF_STRIDE*4);  // [8][256]
    float* qs = smem + 32*BUF_STRIDE*4 + 8*256;          // 512

    const int bi   = blockIdx.x;
    const int b    = bi >> 8;
    const int tid  = threadIdx.x;
    const int warp = tid >> 5;       // head
    const int lane = tid & 31;

    if (tid < 128)
        ((float4*)qs)[tid] = ((const float4*)g_q)[(size_t)bi*128 + tid];

    const float4* ekp = (const float4*)ek  + (size_t)bi*Tv*128;
    const float4* kp  = (const float4*)g_k + (size_t)b *Tv*128;

    const int rbase = tid >> 7;      // 0 or 1
    const int ccol  = tid & 127;

    // ---- Pass A: chunked load+transpose, private dot ----
    for (int c0 = 0; c0 < 8; c0++) {
        __syncthreads();             // buf free (and q ready on first iter)
        #pragma unroll
        for (int u = 0; u < 16; u++) {
            const int r = rbase + 2*u;            // 0..31
            const int j = c0*32 + r;
            const float4 e = ekp[(size_t)j*128 + ccol];
            const float4 k = kp [(size_t)j*128 + ccol];
            float4 s;
            s.x = e.x + k.x; s.y = e.y + k.y; s.z = e.z + k.z; s.w = e.w + k.w;
            buf[r*BUF_STRIDE + ccol] = s;
        }
        __syncthreads();             // buf full

        // thread (head=warp, j=lane): dot over 64 d
        float acc = 0.f;
        #pragma unroll
        for (int g = 0; g < 16; g++) {
            const float4 rv = buf[lane*BUF_STRIDE + warp*16 + g];
            const float4 q4 = ((const float4*)qs)[warp*16 + g];   // broadcast
            acc = fmaf(rv.x, q4.x, fmaf(rv.y, q4.y, fmaf(rv.z, q4.z, fmaf(rv.w, q4.w, acc))));
        }
        sc[warp][c0*32 + lane] = acc;
    }
    __syncwarp();   // each head's row written entirely by its own warp

    // ---- softmax per head (warp-local over 256 j) ----
    const float scale = 0.125f;   // 1/sqrt(64)
    const int* mrow = mask + (size_t)bi * Tv;
    float vbuf[8];
    float mx = -1e30f;
    #pragma unroll
    for (int t = 0; t < 8; t++) {
        const int j = lane + 32*t;
        float s = sc[warp][j];
        s = (mrow[j] == 0) ? -1e9f : s * scale;
        vbuf[t] = s;
        mx = fmaxf(mx, s);
    }
    mx = fmaxf(mx, __shfl_xor_sync(0xffffffffu, mx, 16));
    mx = fmaxf(mx, __shfl_xor_sync(0xffffffffu, mx, 8));
    mx = fmaxf(mx, __shfl_xor_sync(0xffffffffu, mx, 4));
    mx = fmaxf(mx, __shfl_xor_sync(0xffffffffu, mx, 2));
    mx = fmaxf(mx, __shfl_xor_sync(0xffffffffu, mx, 1));
    float sum = 0.f;
    #pragma unroll
    for (int t = 0; t < 8; t++) {
        const float e = expf(vbuf[t] - mx);
        vbuf[t] = e;
        sum += e;
    }
    sum += __shfl_xor_sync(0xffffffffu, sum, 16);
    sum += __shfl_xor_sync(0xffffffffu, sum, 8);
    sum += __shfl_xor_sync(0xffffffffu, sum, 4);
    sum += __shfl_xor_sync(0xffffffffu, sum, 2);
    sum += __shfl_xor_sync(0xffffffffu, sum, 1);
    const float inv = 1.f / sum;
    #pragma unroll
    for (int t = 0; t < 8; t++)
        sc[warp][lane + 32*t] = vbuf[t] * inv;
    __syncwarp();

    // ---- Pass B: vec = sum_j prob*(v + ev), packed (R8) ----
    const float2* evp = (const float2*)ev  + (((size_t)bi*Tv*Ev) >> 1) + warp*32 + lane;
    const float2* vp  = (const float2*)g_v + (((size_t)b *Tv*Ev) >> 1) + warp*32 + lane;
    u64 acc = pk2(0.f, 0.f);
    for (int j0 = 0; j0 < Tv; j0 += 8) {
        float2 re[8], rv[8];
        #pragma unroll
        for (int u = 0; u < 8; u++) re[u] = evp[(size_t)(j0 + u) * 256];
        #pragma unroll
        for (int u = 0; u < 8; u++) rv[u] = vp[(size_t)(j0 + u) * 256];
        #pragma unroll
        for (int u = 0; u < 8; u++) {
            const float p = sc[warp][j0 + u];
            const u64 s = add2(pk2(re[u].x, re[u].y), pk2(rv[u].x, rv[u].y));
            fma2(acc, pk2(p, p), s);
        }
    }
    float a0, a1; upk2(acc, a0, a1);
    g_vec[(size_t)bi*Ev + warp*64 + 2*lane]     = a0;
    g_vec[(size_t)bi*Ev + warp*64 + 2*lane + 1] = a1;
}

// ---------------------------------------------------------------------------
// K3: out = vec @ Wu^T + bu.  BM=32, BN=32, BK=32, 128 threads, 512 CTAs.
// ---------------------------------------------------------------------------
__global__ void __launch_bounds__(128) proj_kernel(const float* __restrict__ Wu,
                                                   const float* __restrict__ bu,
                                                   float* __restrict__ out)
{
    __shared__ float As[32][36];   // [k][r]
    __shared__ float Bs[32][36];   // [k][c]
    const int r0  = blockIdx.x * 32;
    const int c0  = blockIdx.y * 32;
    const int tid = threadIdx.x;
    const int ty  = tid >> 4;       // 0..7  -> rows ty*4..+3
    const int tx  = tid & 15;       // 0..15 -> cols tx*2..+1

    u64 accp[4];
    #pragma unroll
    for (int r = 0; r < 4; r++) accp[r] = pk2(0.f, 0.f);

    for (int k0 = 0; k0 < Ev; k0 += 32) {
        __syncthreads();
        #pragma unroll
        for (int ch = tid; ch < 256; ch += 128) {
            const int r = ch >> 3, k = (ch & 7) * 4;
            const float4 v4 = *(const float4*)&g_vec[(size_t)(r0 + r)*Ev + k0 + k];
            As[k][r] = v4.x; As[k+1][r] = v4.y; As[k+2][r] = v4.z; As[k+3][r] = v4.w;
        }
        #pragma unroll
        for (int ch = tid; ch < 256; ch += 128) {
            const int c = ch >> 3, k = (ch & 7) * 4;
            const float4 v4 = *(const float4*)&Wu[(size_t)(c0 + c)*Ev + k0 + k];
            Bs[k][c] = v4.x; Bs[k+1][c] = v4.y; Bs[k+2][c] = v4.z; Bs[k+3][c] = v4.w;
        }
        __syncthreads();

        #pragma unroll 8
        for (int k = 0; k < 32; k++) {
            const float4 a4 = *(const float4*)&As[k][ty*4];
            const float2 b2 = *(const float2*)&Bs[k][tx*2];
            const u64 bb = pk2(b2.x, b2.y);
            const float a[4] = {a4.x, a4.y, a4.z, a4.w};
            #pragma unroll
            for (int ry = 0; ry < 4; ry++)
                fma2(accp[ry], pk2(a[ry], a[ry]), bb);
        }
    }

    const float2 bias = *(const float2*)&bu[c0 + tx*2];
    #pragma unroll
    for (int ry = 0; ry < 4; ry++) {
        float2 o;
        upk2(accp[ry], o.x, o.y);
        o.x += bias.x; o.y += bias.y;
        *(float2*)&out[(size_t)(r0 + ty*4 + ry)*Ev + c0 + tx*2] = o;
    }
}

// ---------------------------------------------------------------------------
extern "C" void kernel_launch(void* const* d_in, const int* in_sizes, int n_in,
                              void* d_out, int out_size)
{
    const float* x   = (const float*)d_in[0];
    const float* rk  = (const float*)d_in[1];
    const float* rv  = (const float*)d_in[2];
    const int*   msk = (const int*)  d_in[3];
    const float* Wq  = (const float*)d_in[4];
    const float* Wk  = (const float*)d_in[5];
    const float* Wv  = (const float*)d_in[6];
    const float* Wu  = (const float*)d_in[7];
    const float* bu  = (const float*)d_in[8];
    float* out = (float*)d_out;

    cudaFuncSetAttribute(attn_kernel, cudaFuncAttributeMaxDynamicSharedMemorySize,
                         AT_SMEM_BYTES);

    qkv_kernel<<<dim3(16, Hv), 256>>>(x, Wq, Wk, Wv);
    attn_kernel<<<Bv*Tv, 256, AT_SMEM_BYTES>>>(rk, rv, msk);
    proj_kernel<<<dim3(32, 16), 128>>>(Wu, bu, out);
}

// round 11
// speedup vs baseline: 2.3007x; 1.6278x over previous
#include <cuda_runtime.h>

#define Bv 4
#define Tv 256
#define Ev 512
#define Hv 8
#define Sv 64

typedef unsigned long long u64;

// packed fp32x2 helpers (FFMA2 path — ptxas never emits this from C++)
__device__ __forceinline__ u64 pk2(float x, float y) {
    u64 r; asm("mov.b64 %0,{%1,%2};" : "=l"(r) : "f"(x), "f"(y)); return r;
}
__device__ __forceinline__ void upk2(u64 v, float& x, float& y) {
    asm("mov.b64 {%0,%1},%2;" : "=f"(x), "=f"(y) : "l"(v));
}
__device__ __forceinline__ void fma2(u64& d, u64 a, u64 b) {
    asm("fma.rn.f32x2 %0,%1,%2,%0;" : "+l"(d) : "l"(a), "l"(b));
}
__device__ __forceinline__ u64 add2(u64 a, u64 b) {
    u64 r; asm("add.rn.f32x2 %0,%1,%2;" : "=l"(r) : "l"(a), "l"(b)); return r;
}

// scratch (allocation-free rule: __device__ globals)
__device__ float g_q[Bv*Tv*Ev];
__device__ float g_k[Bv*Tv*Ev];
__device__ float g_v[Bv*Tv*Ev];
__device__ float g_scc[Bv*Hv*Tv*Tv];   // [b][n][i][j]
__device__ float g_vec[Bv*Tv*Ev];

// ---------------------------------------------------------------------------
// K1: q/k/v projections (R8 version — measured 13.1us).
// ---------------------------------------------------------------------------
__global__ void __launch_bounds__(256) qkv_kernel(const float* __restrict__ x,
                                                  const float* __restrict__ Wq,
                                                  const float* __restrict__ Wk,
                                                  const float* __restrict__ Wv)
{
    __shared__ float xs[64][68];   // [d][token]
    __shared__ float ws[64][68];   // [d][o]
    const int t0  = blockIdx.x * 64;
    const int n   = blockIdx.y;
    const int tid = threadIdx.x;
    const int ty  = tid >> 4, tx = tid & 15;

    #pragma unroll
    for (int ch = tid; ch < 1024; ch += 256) {
        const int r = ch >> 4, d = (ch & 15) * 4;
        const float4 v4 = *(const float4*)&x[(size_t)(t0 + r)*Ev + n*Sv + d];
        xs[d][r] = v4.x; xs[d+1][r] = v4.y; xs[d+2][r] = v4.z; xs[d+3][r] = v4.w;
    }

    const float* Wlist[3] = {Wq, Wk, Wv};
    float*       Olist[3] = {g_q, g_k, g_v};

    #pragma unroll
    for (int w = 0; w < 3; w++) {
        __syncthreads();
        const float* W = Wlist[w];
        #pragma unroll
        for (int ch = tid; ch < 1024; ch += 256) {
            const int o = ch >> 4, d = (ch & 15) * 4;
            const float4 v4 = *(const float4*)&W[o*Sv + d];
            ws[d][o] = v4.x; ws[d+1][o] = v4.y; ws[d+2][o] = v4.z; ws[d+3][o] = v4.w;
        }
        __syncthreads();

        u64 accp[4][2];
        #pragma unroll
        for (int r = 0; r < 4; r++) { accp[r][0] = pk2(0.f,0.f); accp[r][1] = pk2(0.f,0.f); }

        #pragma unroll 8
        for (int k = 0; k < 64; k++) {
            const float4 a4 = *(const float4*)&xs[k][ty*4];
            const float4 b4 = *(const float4*)&ws[k][tx*4];
            const u64 b01 = pk2(b4.x, b4.y), b23 = pk2(b4.z, b4.w);
            const float a[4] = {a4.x, a4.y, a4.z, a4.w};
            #pragma unroll
            for (int r = 0; r < 4; r++) {
                const u64 aa = pk2(a[r], a[r]);
                fma2(accp[r][0], aa, b01);
                fma2(accp[r][1], aa, b23);
            }
        }

        float* O = Olist[w];
        #pragma unroll
        for (int r = 0; r < 4; r++) {
            float4 o;
            upk2(accp[r][0], o.x, o.y);
            upk2(accp[r][1], o.z, o.w);
            *(float4*)&O[(size_t)(t0 + ty*4 + r)*Ev + n*Sv + tx*4] = o;
        }
    }
}

// ---------------------------------------------------------------------------
// K2: content-content scores (R6 version: K-major smem, FFMA2).
// ---------------------------------------------------------------------------
__global__ void __launch_bounds__(256) scc_kernel()
{
    __shared__ float qs[64][68];   // [d][i-row]
    __shared__ float ks[64][68];   // [d][j-row]
    const int it = blockIdx.x * 64;
    const int jt = blockIdx.y * 64;
    const int b  = blockIdx.z >> 3;
    const int n  = blockIdx.z & 7;
    const int tid = threadIdx.x;

    #pragma unroll
    for (int ch = tid; ch < 1024; ch += 256) {
        const int r = ch >> 4, d = (ch & 15) * 4;
        const float4 q4 = *(const float4*)&g_q[(((size_t)b*Tv + it + r)*Hv + n)*Sv + d];
        qs[d][r] = q4.x; qs[d+1][r] = q4.y; qs[d+2][r] = q4.z; qs[d+3][r] = q4.w;
        const float4 k4 = *(const float4*)&g_k[(((size_t)b*Tv + jt + r)*Hv + n)*Sv + d];
        ks[d][r] = k4.x; ks[d+1][r] = k4.y; ks[d+2][r] = k4.z; ks[d+3][r] = k4.w;
    }
    __syncthreads();

    const int ty = tid >> 4, tx = tid & 15;
    u64 accp[4][2];
    #pragma unroll
    for (int r = 0; r < 4; r++) { accp[r][0] = pk2(0.f,0.f); accp[r][1] = pk2(0.f,0.f); }

    #pragma unroll 8
    for (int d = 0; d < 64; d++) {
        const float4 a4 = *(const float4*)&qs[d][ty*4];
        const float4 c4 = *(const float4*)&ks[d][tx*4];
        const u64 c01 = pk2(c4.x, c4.y), c23 = pk2(c4.z, c4.w);
        const float a[4] = {a4.x, a4.y, a4.z, a4.w};
        #pragma unroll
        for (int r = 0; r < 4; r++) {
            const u64 aa = pk2(a[r], a[r]);
            fma2(accp[r][0], aa, c01);
            fma2(accp[r][1], aa, c23);
        }
    }

    #pragma unroll
    for (int r = 0; r < 4; r++) {
        float4 o;
        upk2(accp[r][0], o.x, o.y);
        upk2(accp[r][1], o.z, o.w);
        *(float4*)&g_scc[(((size_t)b*Hv + n)*Tv + it + ty*4 + r)*Tv + jt + tx*4] = o;
    }
}

// ---------------------------------------------------------------------------
// K3: streaming attention (R6 attn = best measured ~165us):
// sc preload, Pass A streams ek ONLY (no k — keeps LTS below cap),
// barrier-free 8-deep MLP, packed Pass B with ev + L2 v.
// ---------------------------------------------------------------------------
__global__ void __launch_bounds__(256) attn_kernel(const float* __restrict__ ek,
                                                   const float* __restrict__ ev,
                                                   const int*   __restrict__ mask)
{
    __shared__ float sc[Hv][Tv];     // scores -> probs
    __shared__ float qsm[Ev];

    const int bi   = blockIdx.x;
    const int b    = bi >> 8;
    const int i    = bi & 255;
    const int tid  = threadIdx.x;
    const int warp = tid >> 5;
    const int lane = tid & 31;

    qsm[tid]       = g_q[(size_t)bi*Ev + tid];
    qsm[tid + 256] = g_q[(size_t)bi*Ev + tid + 256];

    // preload content-content scores: sc[n][j]
    #pragma unroll
    for (int t = 0; t < 8; t++)
        sc[t][tid] = g_scc[(((size_t)b*Hv + t)*Tv + i)*Tv + tid];
    __syncthreads();

    const float q0 = qsm[warp*64 + 2*lane];
    const float q1 = qsm[warp*64 + 2*lane + 1];

    const float2* ekp = (const float2*)ek + (((size_t)bi*Tv*Ev) >> 1) + warp*32 + lane;

    // ---- Pass A: stream ek, add q.ek to scores ----
    for (int j0 = 0; j0 < Tv; j0 += 8) {
        float2 r[8];
        #pragma unroll
        for (int u = 0; u < 8; u++) r[u] = ekp[(size_t)(j0 + u) * 256];
        #pragma unroll
        for (int u = 0; u < 8; u++) {
            float p = fmaf(r[u].x, q0, r[u].y * q1);
            p += __shfl_xor_sync(0xffffffffu, p, 16);
            p += __shfl_xor_sync(0xffffffffu, p, 8);
            p += __shfl_xor_sync(0xffffffffu, p, 4);
            p += __shfl_xor_sync(0xffffffffu, p, 2);
            p += __shfl_xor_sync(0xffffffffu, p, 1);
            if (lane == 0) sc[warp][j0 + u] += p;
        }
    }
    __syncwarp();

    // ---- softmax per head (warp-local over 256 j) ----
    const float scale = 0.125f;   // 1/sqrt(64)
    const int* mrow = mask + (size_t)bi * Tv;
    float vbuf[8];
    float mx = -1e30f;
    #pragma unroll
    for (int t = 0; t < 8; t++) {
        const int j = lane + 32*t;
        float s = sc[warp][j];
        s = (mrow[j] == 0) ? -1e9f : s * scale;
        vbuf[t] = s;
        mx = fmaxf(mx, s);
    }
    mx = fmaxf(mx, __shfl_xor_sync(0xffffffffu, mx, 16));
    mx = fmaxf(mx, __shfl_xor_sync(0xffffffffu, mx, 8));
    mx = fmaxf(mx, __shfl_xor_sync(0xffffffffu, mx, 4));
    mx = fmaxf(mx, __shfl_xor_sync(0xffffffffu, mx, 2));
    mx = fmaxf(mx, __shfl_xor_sync(0xffffffffu, mx, 1));
    float sum = 0.f;
    #pragma unroll
    for (int t = 0; t < 8; t++) {
        const float e = expf(vbuf[t] - mx);
        vbuf[t] = e;
        sum += e;
    }
    sum += __shfl_xor_sync(0xffffffffu, sum, 16);
    sum += __shfl_xor_sync(0xffffffffu, sum, 8);
    sum += __shfl_xor_sync(0xffffffffu, sum, 4);
    sum += __shfl_xor_sync(0xffffffffu, sum, 2);
    sum += __shfl_xor_sync(0xffffffffu, sum, 1);
    const float inv = 1.f / sum;
    #pragma unroll
    for (int t = 0; t < 8; t++)
        sc[warp][lane + 32*t] = vbuf[t] * inv;
    __syncwarp();

    // ---- Pass B: stream ev + L2-hit v, packed accumulate ----
    const float2* evp = (const float2*)ev  + (((size_t)bi*Tv*Ev) >> 1) + warp*32 + lane;
    const float2* vp  = (const float2*)g_v + (((size_t)b *Tv*Ev) >> 1) + warp*32 + lane;
    u64 acc = pk2(0.f, 0.f);
    for (int j0 = 0; j0 < Tv; j0 += 8) {
        float2 re[8], rv[8];
        #pragma unroll
        for (int u = 0; u < 8; u++) re[u] = evp[(size_t)(j0 + u) * 256];
        #pragma unroll
        for (int u = 0; u < 8; u++) rv[u] = vp[(size_t)(j0 + u) * 256];
        #pragma unroll
        for (int u = 0; u < 8; u++) {
            const float p = sc[warp][j0 + u];
            const u64 s = add2(pk2(re[u].x, re[u].y), pk2(rv[u].x, rv[u].y));
            fma2(acc, pk2(p, p), s);
        }
    }
    float a0, a1; upk2(acc, a0, a1);
    g_vec[(size_t)bi*Ev + warp*64 + 2*lane]     = a0;
    g_vec[(size_t)bi*Ev + warp*64 + 2*lane + 1] = a1;
}

// ---------------------------------------------------------------------------
// K4: out = vec @ Wu^T + bu.  BM=32, BN=32, BK=32, 128 threads, 512 CTAs.
// ---------------------------------------------------------------------------
__global__ void __launch_bounds__(128) proj_kernel(const float* __restrict__ Wu,
                                                   const float* __restrict__ bu,
                                                   float* __restrict__ out)
{
    __shared__ float As[32][36];   // [k][r]
    __shared__ float Bs[32][36];   // [k][c]
    const int r0  = blockIdx.x * 32;
    const int c0  = blockIdx.y * 32;
    const int tid = threadIdx.x;
    const int ty  = tid >> 4;       // 0..7  -> rows ty*4..+3
    const int tx  = tid & 15;       // 0..15 -> cols tx*2..+1

    u64 accp[4];
    #pragma unroll
    for (int r = 0; r < 4; r++) accp[r] = pk2(0.f, 0.f);

    for (int k0 = 0; k0 < Ev; k0 += 32) {
        __syncthreads();
        #pragma unroll
        for (int ch = tid; ch < 256; ch += 128) {
            const int r = ch >> 3, k = (ch & 7) * 4;
            const float4 v4 = *(const float4*)&g_vec[(size_t)(r0 + r)*Ev + k0 + k];
            As[k][r] = v4.x; As[k+1][r] = v4.y; As[k+2][r] = v4.z; As[k+3][r] = v4.w;
        }
        #pragma unroll
        for (int ch = tid; ch < 256; ch += 128) {
            const int c = ch >> 3, k = (ch & 7) * 4;
            const float4 v4 = *(const float4*)&Wu[(size_t)(c0 + c)*Ev + k0 + k];
            Bs[k][c] = v4.x; Bs[k+1][c] = v4.y; Bs[k+2][c] = v4.z; Bs[k+3][c] = v4.w;
        }
        __syncthreads();

        #pragma unroll 8
        for (int k = 0; k < 32; k++) {
            const float4 a4 = *(const float4*)&As[k][ty*4];
            const float2 b2 = *(const float2*)&Bs[k][tx*2];
            const u64 bb = pk2(b2.x, b2.y);
            const float a[4] = {a4.x, a4.y, a4.z, a4.w};
            #pragma unroll
            for (int ry = 0; ry < 4; ry++)
                fma2(accp[ry], pk2(a[ry], a[ry]), bb);
        }
    }

    const float2 bias = *(const float2*)&bu[c0 + tx*2];
    #pragma unroll
    for (int ry = 0; ry < 4; ry++) {
        float2 o;
        upk2(accp[ry], o.x, o.y);
        o.x += bias.x; o.y += bias.y;
        *(float2*)&out[(size_t)(r0 + ty*4 + ry)*Ev + c0 + tx*2] = o;
    }
}

// ---------------------------------------------------------------------------
extern "C" void kernel_launch(void* const* d_in, const int* in_sizes, int n_in,
                              void* d_out, int out_size)
{
    const float* x   = (const float*)d_in[0];
    const float* rk  = (const float*)d_in[1];
    const float* rv  = (const float*)d_in[2];
    const int*   msk = (const int*)  d_in[3];
    const float* Wq  = (const float*)d_in[4];
    const float* Wk  = (const float*)d_in[5];
    const float* Wv  = (const float*)d_in[6];
    const float* Wu  = (const float*)d_in[7];
    const float* bu  = (const float*)d_in[8];
    float* out = (float*)d_out;

    qkv_kernel<<<dim3(16, Hv), 256>>>(x, Wq, Wk, Wv);
    scc_kernel<<<dim3(4, 4, Bv*Hv), 256>>>();
    attn_kernel<<<Bv*Tv, 256>>>(rk, rv, msk);
    proj_kernel<<<dim3(32, 16), 128>>>(Wu, bu, out);
}

// round 12
// speedup vs baseline: 2.4779x; 1.0770x over previous
#include <cuda_runtime.h>

#define Bv 4
#define Tv 256
#define Ev 512
#define Hv 8
#define Sv 64

typedef unsigned long long u64;

// packed fp32x2 helpers (FFMA2 path — ptxas never emits this from C++)
__device__ __forceinline__ u64 pk2(float x, float y) {
    u64 r; asm("mov.b64 %0,{%1,%2};" : "=l"(r) : "f"(x), "f"(y)); return r;
}
__device__ __forceinline__ void upk2(u64 v, float& x, float& y) {
    asm("mov.b64 {%0,%1},%2;" : "=f"(x), "=f"(y) : "l"(v));
}
__device__ __forceinline__ void fma2(u64& d, u64 a, u64 b) {
    asm("fma.rn.f32x2 %0,%1,%2,%0;" : "+l"(d) : "l"(a), "l"(b));
}
__device__ __forceinline__ u64 add2(u64 a, u64 b) {
    u64 r; asm("add.rn.f32x2 %0,%1,%2;" : "=l"(r) : "l"(a), "l"(b)); return r;
}

// scratch (allocation-free rule: __device__ globals)
__device__ float g_q[Bv*Tv*Ev];
__device__ float g_k[Bv*Tv*Ev];
__device__ float g_v[Bv*Tv*Ev];
__device__ float g_vec[Bv*Tv*Ev];

// ---------------------------------------------------------------------------
// K1: q/k/v projections (R8 version — measured 13.1us).
// ---------------------------------------------------------------------------
__global__ void __launch_bounds__(256) qkv_kernel(const float* __restrict__ x,
                                                  const float* __restrict__ Wq,
                                                  const float* __restrict__ Wk,
                                                  const float* __restrict__ Wv)
{
    __shared__ float xs[64][68];   // [d][token]
    __shared__ float ws[64][68];   // [d][o]
    const int t0  = blockIdx.x * 64;
    const int n   = blockIdx.y;
    const int tid = threadIdx.x;
    const int ty  = tid >> 4, tx = tid & 15;

    #pragma unroll
    for (int ch = tid; ch < 1024; ch += 256) {
        const int r = ch >> 4, d = (ch & 15) * 4;
        const float4 v4 = *(const float4*)&x[(size_t)(t0 + r)*Ev + n*Sv + d];
        xs[d][r] = v4.x; xs[d+1][r] = v4.y; xs[d+2][r] = v4.z; xs[d+3][r] = v4.w;
    }

    const float* Wlist[3] = {Wq, Wk, Wv};
    float*       Olist[3] = {g_q, g_k, g_v};

    #pragma unroll
    for (int w = 0; w < 3; w++) {
        __syncthreads();
        const float* W = Wlist[w];
        #pragma unroll
        for (int ch = tid; ch < 1024; ch += 256) {
            const int o = ch >> 4, d = (ch & 15) * 4;
            const float4 v4 = *(const float4*)&W[o*Sv + d];
            ws[d][o] = v4.x; ws[d+1][o] = v4.y; ws[d+2][o] = v4.z; ws[d+3][o] = v4.w;
        }
        __syncthreads();

        u64 accp[4][2];
        #pragma unroll
        for (int r = 0; r < 4; r++) { accp[r][0] = pk2(0.f,0.f); accp[r][1] = pk2(0.f,0.f); }

        #pragma unroll 8
        for (int k = 0; k < 64; k++) {
            const float4 a4 = *(const float4*)&xs[k][ty*4];
            const float4 b4 = *(const float4*)&ws[k][tx*4];
            const u64 b01 = pk2(b4.x, b4.y), b23 = pk2(b4.z, b4.w);
            const float a[4] = {a4.x, a4.y, a4.z, a4.w};
            #pragma unroll
            for (int r = 0; r < 4; r++) {
                const u64 aa = pk2(a[r], a[r]);
                fma2(accp[r][0], aa, b01);
                fma2(accp[r][1], aa, b23);
            }
        }

        float* O = Olist[w];
        #pragma unroll
        for (int r = 0; r < 4; r++) {
            float4 o;
            upk2(accp[r][0], o.x, o.y);
            upk2(accp[r][1], o.z, o.w);
            *(float4*)&O[(size_t)(t0 + ty*4 + r)*Ev + n*Sv + tx*4] = o;
        }
    }
}

// ---------------------------------------------------------------------------
// K2: fused attention (R8 version — measured ~168us, near DRAM floor).
// Pass A: score = q.(k + ek); Pass B: vec = sum prob*(v + ev).
// ---------------------------------------------------------------------------
__global__ void __launch_bounds__(256) attn_kernel(const float* __restrict__ ek,
                                                   const float* __restrict__ ev,
                                                   const int*   __restrict__ mask)
{
    __shared__ float sc[Hv][Tv];     // scores -> probs
    __shared__ float qsm[Ev];

    const int bi   = blockIdx.x;
    const int b    = bi >> 8;
    const int tid  = threadIdx.x;
    const int warp = tid >> 5;
    const int lane = tid & 31;

    qsm[tid]       = g_q[(size_t)bi*Ev + tid];
    qsm[tid + 256] = g_q[(size_t)bi*Ev + tid + 256];
    __syncthreads();

    const float q0 = qsm[warp*64 + 2*lane];
    const float q1 = qsm[warp*64 + 2*lane + 1];

    const float2* ekp = (const float2*)ek  + (((size_t)bi*Tv*Ev) >> 1) + warp*32 + lane;
    const float2* kp  = (const float2*)g_k + (((size_t)b *Tv*Ev) >> 1) + warp*32 + lane;

    // ---- Pass A: score = q.(k + ek), single shuffle tree ----
    for (int j0 = 0; j0 < Tv; j0 += 8) {
        float2 re[8], rk[8];
        #pragma unroll
        for (int u = 0; u < 8; u++) re[u] = ekp[(size_t)(j0 + u) * 256];
        #pragma unroll
        for (int u = 0; u < 8; u++) rk[u] = kp[(size_t)(j0 + u) * 256];
        #pragma unroll
        for (int u = 0; u < 8; u++) {
            const float sx = re[u].x + rk[u].x;
            const float sy = re[u].y + rk[u].y;
            float p = fmaf(sx, q0, sy * q1);
            p += __shfl_xor_sync(0xffffffffu, p, 16);
            p += __shfl_xor_sync(0xffffffffu, p, 8);
            p += __shfl_xor_sync(0xffffffffu, p, 4);
            p += __shfl_xor_sync(0xffffffffu, p, 2);
            p += __shfl_xor_sync(0xffffffffu, p, 1);
            if (lane == 0) sc[warp][j0 + u] = p;
        }
    }
    __syncwarp();

    // ---- softmax per head (warp-local over 256 j) ----
    const float scale = 0.125f;   // 1/sqrt(64)
    const int* mrow = mask + (size_t)bi * Tv;
    float vbuf[8];
    float mx = -1e30f;
    #pragma unroll
    for (int t = 0; t < 8; t++) {
        const int j = lane + 32*t;
        float s = sc[warp][j];
        s = (mrow[j] == 0) ? -1e9f : s * scale;
        vbuf[t] = s;
        mx = fmaxf(mx, s);
    }
    mx = fmaxf(mx, __shfl_xor_sync(0xffffffffu, mx, 16));
    mx = fmaxf(mx, __shfl_xor_sync(0xffffffffu, mx, 8));
    mx = fmaxf(mx, __shfl_xor_sync(0xffffffffu, mx, 4));
    mx = fmaxf(mx, __shfl_xor_sync(0xffffffffu, mx, 2));
    mx = fmaxf(mx, __shfl_xor_sync(0xffffffffu, mx, 1));
    float sum = 0.f;
    #pragma unroll
    for (int t = 0; t < 8; t++) {
        const float e = expf(vbuf[t] - mx);
        vbuf[t] = e;
        sum += e;
    }
    sum += __shfl_xor_sync(0xffffffffu, sum, 16);
    sum += __shfl_xor_sync(0xffffffffu, sum, 8);
    sum += __shfl_xor_sync(0xffffffffu, sum, 4);
    sum += __shfl_xor_sync(0xffffffffu, sum, 2);
    sum += __shfl_xor_sync(0xffffffffu, sum, 1);
    const float inv = 1.f / sum;
    #pragma unroll
    for (int t = 0; t < 8; t++)
        sc[warp][lane + 32*t] = vbuf[t] * inv;
    __syncwarp();

    // ---- Pass B: stream ev + L2 v, packed accumulate ----
    const float2* evp = (const float2*)ev  + (((size_t)bi*Tv*Ev) >> 1) + warp*32 + lane;
    const float2* vp  = (const float2*)g_v + (((size_t)b *Tv*Ev) >> 1) + warp*32 + lane;
    u64 acc = pk2(0.f, 0.f);
    for (int j0 = 0; j0 < Tv; j0 += 8) {
        float2 re[8], rv[8];
        #pragma unroll
        for (int u = 0; u < 8; u++) re[u] = evp[(size_t)(j0 + u) * 256];
        #pragma unroll
        for (int u = 0; u < 8; u++) rv[u] = vp[(size_t)(j0 + u) * 256];
        #pragma unroll
        for (int u = 0; u < 8; u++) {
            const float p = sc[warp][j0 + u];
            const u64 s = add2(pk2(re[u].x, re[u].y), pk2(rv[u].x, rv[u].y));
            fma2(acc, pk2(p, p), s);
        }
    }
    float a0, a1; upk2(acc, a0, a1);
    g_vec[(size_t)bi*Ev + warp*64 + 2*lane]     = a0;
    g_vec[(size_t)bi*Ev + warp*64 + 2*lane + 1] = a1;
}

// ---------------------------------------------------------------------------
// K3: out = vec @ Wu^T + bu.  BM=64, BN=32, BK=32, 128 threads, 256 CTAs.
// Double-buffered smem with register prefetch; ONE __syncthreads per K-step.
// ---------------------------------------------------------------------------
__global__ void __launch_bounds__(128) proj_kernel(const float* __restrict__ Wu,
                                                   const float* __restrict__ bu,
                                                   float* __restrict__ out)
{
    __shared__ float As[2][32][68];   // [buf][k][r]  r0..r0+63
    __shared__ float Bs[2][32][36];   // [buf][k][c]  c0..c0+31
    const int r0  = blockIdx.x * 64;
    const int c0  = blockIdx.y * 32;
    const int tid = threadIdx.x;
    const int ty  = tid >> 3;       // 0..15 -> rows ty*4..+3
    const int tx  = tid & 7;        // 0..7  -> cols tx*4..+3

    const int ar = tid >> 3;        // A chunk row base (0..15), +16 per step
    const int ak = (tid & 7) * 4;   // A chunk k
    const int br = tid >> 3;        // B chunk row base
    const int bk = (tid & 7) * 4;

    float4 pa[4], pb[2];

    // prefetch tile 0 into regs
    #pragma unroll
    for (int i = 0; i < 4; i++)
        pa[i] = *(const float4*)&g_vec[(size_t)(r0 + ar + i*16)*Ev + ak];
    #pragma unroll
    for (int i = 0; i < 2; i++)
        pb[i] = *(const float4*)&Wu[(size_t)(c0 + br + i*16)*Ev + bk];

    // store tile 0
    #pragma unroll
    for (int i = 0; i < 4; i++) {
        const int r = ar + i*16;
        As[0][ak][r] = pa[i].x; As[0][ak+1][r] = pa[i].y;
        As[0][ak+2][r] = pa[i].z; As[0][ak+3][r] = pa[i].w;
    }
    #pragma unroll
    for (int i = 0; i < 2; i++) {
        const int c = br + i*16;
        Bs[0][bk][c] = pb[i].x; Bs[0][bk+1][c] = pb[i].y;
        Bs[0][bk+2][c] = pb[i].z; Bs[0][bk+3][c] = pb[i].w;
    }
    __syncthreads();

    u64 accp[4][2];
    #pragma unroll
    for (int r = 0; r < 4; r++) { accp[r][0] = pk2(0.f,0.f); accp[r][1] = pk2(0.f,0.f); }

    for (int t = 0; t < 16; t++) {
        const int cur = t & 1, nxt = cur ^ 1;

        // prefetch tile t+1 into regs (overlaps with compute below)
        if (t < 15) {
            const int k0 = (t + 1) * 32;
            #pragma unroll
            for (int i = 0; i < 4; i++)
                pa[i] = *(const float4*)&g_vec[(size_t)(r0 + ar + i*16)*Ev + k0 + ak];
            #pragma unroll
            for (int i = 0; i < 2; i++)
                pb[i] = *(const float4*)&Wu[(size_t)(c0 + br + i*16)*Ev + k0 + bk];
        }

        #pragma unroll 8
        for (int k = 0; k < 32; k++) {
            const float4 a4 = *(const float4*)&As[cur][k][ty*4];
            const float4 b4 = *(const float4*)&Bs[cur][k][tx*4];
            const u64 b01 = pk2(b4.x, b4.y), b23 = pk2(b4.z, b4.w);
            const float a[4] = {a4.x, a4.y, a4.z, a4.w};
            #pragma unroll
            for (int ry = 0; ry < 4; ry++) {
                const u64 aa = pk2(a[ry], a[ry]);
                fma2(accp[ry][0], aa, b01);
                fma2(accp[ry][1], aa, b23);
            }
        }

        if (t < 15) {
            #pragma unroll
            for (int i = 0; i < 4; i++) {
                const int r = ar + i*16;
                As[nxt][ak][r] = pa[i].x; As[nxt][ak+1][r] = pa[i].y;
                As[nxt][ak+2][r] = pa[i].z; As[nxt][ak+3][r] = pa[i].w;
            }
            #pragma unroll
            for (int i = 0; i < 2; i++) {
                const int c = br + i*16;
                Bs[nxt][bk][c] = pb[i].x; Bs[nxt][bk+1][c] = pb[i].y;
                Bs[nxt][bk+2][c] = pb[i].z; Bs[nxt][bk+3][c] = pb[i].w;
            }
            __syncthreads();
        }
    }

    const float4 bias = *(const float4*)&bu[c0 + tx*4];
    #pragma unroll
    for (int ry = 0; ry < 4; ry++) {
        float4 o;
        upk2(accp[ry][0], o.x, o.y);
        upk2(accp[ry][1], o.z, o.w);
        o.x += bias.x; o.y += bias.y; o.z += bias.z; o.w += bias.w;
        *(float4*)&out[(size_t)(r0 + ty*4 + ry)*Ev + c0 + tx*4] = o;
    }
}

// ---------------------------------------------------------------------------
extern "C" void kernel_launch(void* const* d_in, const int* in_sizes, int n_in,
                              void* d_out, int out_size)
{
    const float* x   = (const float*)d_in[0];
    const float* rk  = (const float*)d_in[1];
    const float* rv  = (const float*)d_in[2];
    const int*   msk = (const int*)  d_in[3];
    const float* Wq  = (const float*)d_in[4];
    const float* Wk  = (const float*)d_in[5];
    const float* Wv  = (const float*)d_in[6];
    const float* Wu  = (const float*)d_in[7];
    const float* bu  = (const float*)d_in[8];
    float* out = (float*)d_out;

    qkv_kernel<<<dim3(16, Hv), 256>>>(x, Wq, Wk, Wv);
    attn_kernel<<<Bv*Tv, 256>>>(rk, rv, msk);
    proj_kernel<<<dim3(16, 16), 128>>>(Wu, bu, out);
}